// round 1
// baseline (speedup 1.0000x reference)
#include <cuda_runtime.h>

#define BATCH 16
#define NPTS  4096
#define CIN   64
#define NSAMP 1024
#define KNBR  32
#define FULLM 0xffffffffu

// scratch: ball-query neighbor indices
__device__ int d_ball[BATCH * NSAMP * KNBR];

// ---------------------------------------------------------------------------
// Kernel 1: farthest point sampling. One block per batch, 1024 threads,
// 4 points per thread in registers, xyz in shared. Writes new_xyz directly
// into the first section of d_out.
// ---------------------------------------------------------------------------
__global__ __launch_bounds__(1024) void fps_kernel(const float* __restrict__ xyz,
                                                   float* __restrict__ new_xyz)
{
    extern __shared__ float sm[];
    float* sxyz = sm;                   // 4096*3
    float* redv = sm + NPTS * 3;        // 32
    int*   redi = (int*)(redv + 32);    // 32
    int*   sfar = redi + 32;            // 1

    const int b   = blockIdx.x;
    const int tid = threadIdx.x;
    const float* gx = xyz + (size_t)b * NPTS * 3;

    for (int i = tid; i < NPTS * 3; i += 1024) sxyz[i] = gx[i];
    __syncthreads();

    float px[4], py[4], pz[4], dist[4];
#pragma unroll
    for (int j = 0; j < 4; j++) {
        int p = tid + j * 1024;
        px[j] = sxyz[3 * p];
        py[j] = sxyz[3 * p + 1];
        pz[j] = sxyz[3 * p + 2];
        dist[j] = 1e10f;
    }

    const int lane = tid & 31, warp = tid >> 5;
    int far = 0;

    for (int t = 0; t < NSAMP; t++) {
        float cx = sxyz[3 * far], cy = sxyz[3 * far + 1], cz = sxyz[3 * far + 2];
        if (tid == 0) {
            float* o = new_xyz + ((size_t)b * NSAMP + t) * 3;
            o[0] = cx; o[1] = cy; o[2] = cz;
        }
        float bv = -1.0f; int bi = 0;
#pragma unroll
        for (int j = 0; j < 4; j++) {
            float dx = __fsub_rn(px[j], cx);
            float dy = __fsub_rn(py[j], cy);
            float dz = __fsub_rn(pz[j], cz);
            float d2 = __fadd_rn(__fadd_rn(__fmul_rn(dx, dx), __fmul_rn(dy, dy)),
                                 __fmul_rn(dz, dz));
            float nd = fminf(dist[j], d2);
            dist[j] = nd;
            if (nd > bv) { bv = nd; bi = tid + j * 1024; }
        }
        // warp argmax (max value, min index tie-break -> matches jnp.argmax)
#pragma unroll
        for (int o = 16; o; o >>= 1) {
            float v2 = __shfl_xor_sync(FULLM, bv, o);
            int   i2 = __shfl_xor_sync(FULLM, bi, o);
            if (v2 > bv || (v2 == bv && i2 < bi)) { bv = v2; bi = i2; }
        }
        if (lane == 0) { redv[warp] = bv; redi[warp] = bi; }
        __syncthreads();
        if (warp == 0) {
            float v = redv[lane]; int i = redi[lane];
#pragma unroll
            for (int o = 16; o; o >>= 1) {
                float v2 = __shfl_xor_sync(FULLM, v, o);
                int   i2 = __shfl_xor_sync(FULLM, i, o);
                if (v2 > v || (v2 == v && i2 < i)) { v = v2; i = i2; }
            }
            if (lane == 0) sfar[0] = i;
        }
        __syncthreads();
        far = sfar[0];
    }
}

// ---------------------------------------------------------------------------
// Kernel 2: ball query. One warp per centroid; ordered scan via ballot/popc,
// early exit once KNBR found; pad with first index.
// ---------------------------------------------------------------------------
__global__ __launch_bounds__(256) void query_kernel(const float* __restrict__ xyz,
                                                    const float* __restrict__ new_xyz)
{
    const int warp = threadIdx.x >> 5, lane = threadIdx.x & 31;
    const int gs = blockIdx.x * 8 + warp;     // global centroid id
    const int b  = gs >> 10;
    const float* nc = new_xyz + (size_t)gs * 3;
    const float cx = nc[0], cy = nc[1], cz = nc[2];
    const float* gx = xyz + (size_t)b * NPTS * 3;
    int* out = d_ball + (size_t)gs * KNBR;
    const float R2 = 0.04f;                   // f32(0.2*0.2) as JAX sees it

    int cnt = 0;
    int first = -1;
    for (int base = 0; base < NPTS && cnt < KNBR; base += 32) {
        int j = base + lane;
        float dx = __fsub_rn(cx, gx[3 * j]);
        float dy = __fsub_rn(cy, gx[3 * j + 1]);
        float dz = __fsub_rn(cz, gx[3 * j + 2]);
        float d2 = __fadd_rn(__fadd_rn(__fmul_rn(dx, dx), __fmul_rn(dy, dy)),
                             __fmul_rn(dz, dz));
        bool in = (d2 <= R2);
        unsigned m = __ballot_sync(FULLM, in);
        int pos = cnt + __popc(m & ((1u << lane) - 1u));
        if (in && pos < KNBR) {
            out[pos] = j;
            if (pos == 0) first = j;
        }
        cnt += __popc(m);
    }
    unsigned hf = __ballot_sync(FULLM, first >= 0);
    int src = __ffs(hf) - 1;
    first = __shfl_sync(FULLM, first, src);
    int filled = cnt < KNBR ? cnt : KNBR;
    if (lane >= filled) out[lane] = first;
}

// ---------------------------------------------------------------------------
// Kernel 3: fused gather + 3-layer MLP + max pool. lane = neighbor k (K=32),
// warp = centroid, 8 centroids/block. Weights + per-thread activation
// columns in shared. Max pool over k = warp shuffle reduce.
// ---------------------------------------------------------------------------
__global__ __launch_bounds__(256) void mlp_kernel(
    const float* __restrict__ xyz, const float* __restrict__ pts,
    const float* __restrict__ w0, const float* __restrict__ b0,
    const float* __restrict__ w1, const float* __restrict__ b1,
    const float* __restrict__ w2, const float* __restrict__ b2,
    const float* __restrict__ new_xyz, float* __restrict__ new_points)
{
    extern __shared__ float sm[];
    float* w0s = sm;                 // 67*64 = 4288
    float* b0s = w0s + 4288;         // 64
    float* w1s = b0s + 64;           // 64*64 = 4096
    float* b1s = w1s + 4096;         // 64
    float* w2s = b1s + 64;           // 64*128 = 8192
    float* b2s = w2s + 8192;         // 128
    float* buf = b2s + 128;          // 67 * 256 activation columns

    const int tid = threadIdx.x;
    for (int i = tid; i < 4288; i += 256) w0s[i] = w0[i];
    for (int i = tid; i < 64;   i += 256) b0s[i] = b0[i];
    for (int i = tid; i < 4096; i += 256) w1s[i] = w1[i];
    for (int i = tid; i < 64;   i += 256) b1s[i] = b1[i];
    for (int i = tid; i < 8192; i += 256) w2s[i] = w2[i];
    for (int i = tid; i < 128;  i += 256) b2s[i] = b2[i];

    const int warp = tid >> 5, lane = tid & 31;
    const int gs = blockIdx.x * 8 + warp;
    const int b  = gs >> 10;
    const int nid = d_ball[(size_t)gs * KNBR + lane];

    // gather input row: 64 point features + 3 relative xyz
    const float4* pr = (const float4*)(pts + ((size_t)b * NPTS + nid) * CIN);
#pragma unroll
    for (int q = 0; q < 16; q++) {
        float4 v = pr[q];
        buf[(4 * q + 0) * 256 + tid] = v.x;
        buf[(4 * q + 1) * 256 + tid] = v.y;
        buf[(4 * q + 2) * 256 + tid] = v.z;
        buf[(4 * q + 3) * 256 + tid] = v.w;
    }
    {
        const float* xr = xyz + ((size_t)b * NPTS + nid) * 3;
        const float* nc = new_xyz + (size_t)gs * 3;
        buf[64 * 256 + tid] = __fsub_rn(xr[0], nc[0]);
        buf[65 * 256 + tid] = __fsub_rn(xr[1], nc[1]);
        buf[66 * 256 + tid] = __fsub_rn(xr[2], nc[2]);
    }
    __syncthreads();   // weights ready (buf columns are thread-private)

    // ---- layer 1: 67 -> 64 ----
    float a[64];
#pragma unroll
    for (int ch = 0; ch < 4; ch++) {
        float acc[16];
#pragma unroll
        for (int j = 0; j < 16; j++) acc[j] = b0s[ch * 16 + j];
        for (int c = 0; c < 67; c++) {
            float x = buf[c * 256 + tid];
            const float* wr = w0s + c * 64 + ch * 16;
#pragma unroll
            for (int j = 0; j < 16; j++) acc[j] = fmaf(x, wr[j], acc[j]);
        }
#pragma unroll
        for (int j = 0; j < 16; j++) a[ch * 16 + j] = fmaxf(acc[j], 0.f);
    }
#pragma unroll
    for (int c = 0; c < 64; c++) buf[c * 256 + tid] = a[c];

    // ---- layer 2: 64 -> 64 ----
#pragma unroll
    for (int ch = 0; ch < 4; ch++) {
        float acc[16];
#pragma unroll
        for (int j = 0; j < 16; j++) acc[j] = b1s[ch * 16 + j];
        for (int c = 0; c < 64; c++) {
            float x = buf[c * 256 + tid];
            const float* wr = w1s + c * 64 + ch * 16;
#pragma unroll
            for (int j = 0; j < 16; j++) acc[j] = fmaf(x, wr[j], acc[j]);
        }
#pragma unroll
        for (int j = 0; j < 16; j++) a[ch * 16 + j] = fmaxf(acc[j], 0.f);
    }
#pragma unroll
    for (int c = 0; c < 64; c++) buf[c * 256 + tid] = a[c];

    // ---- layer 3: 64 -> 128, fused relu + max pool over k (warp) ----
    float* outp = new_points + (size_t)gs * 128;
#pragma unroll
    for (int ch = 0; ch < 4; ch++) {
        float acc[32];
#pragma unroll
        for (int j = 0; j < 32; j++) acc[j] = b2s[ch * 32 + j];
        for (int c = 0; c < 64; c++) {
            float x = buf[c * 256 + tid];
            const float* wr = w2s + c * 128 + ch * 32;
#pragma unroll
            for (int j = 0; j < 32; j++) acc[j] = fmaf(x, wr[j], acc[j]);
        }
        float res = 0.f;
#pragma unroll
        for (int f = 0; f < 32; f++) {
            float v = fmaxf(acc[f], 0.f);
#pragma unroll
            for (int o = 16; o; o >>= 1) v = fmaxf(v, __shfl_xor_sync(FULLM, v, o));
            if (lane == f) res = v;
        }
        outp[ch * 32 + lane] = res;
    }
}

// ---------------------------------------------------------------------------
extern "C" void kernel_launch(void* const* d_in, const int* in_sizes, int n_in,
                              void* d_out, int out_size)
{
    (void)in_sizes; (void)n_in; (void)out_size;
    const float* xyz = (const float*)d_in[0];
    const float* pts = (const float*)d_in[1];
    const float* w0  = (const float*)d_in[2];
    const float* b0  = (const float*)d_in[3];
    const float* w1  = (const float*)d_in[4];
    const float* b1  = (const float*)d_in[5];
    const float* w2  = (const float*)d_in[6];
    const float* b2  = (const float*)d_in[7];

    float* out      = (float*)d_out;
    float* new_xyz  = out;                              // 16*1024*3
    float* new_pts  = out + (size_t)BATCH * NSAMP * 3;  // 16*1024*128

    const int FPS_SMEM = (NPTS * 3) * 4 + 32 * 4 + 32 * 4 + 16;        // ~49.4 KB
    const int MLP_SMEM = (4288 + 64 + 4096 + 64 + 8192 + 128 + 67 * 256) * 4; // ~136 KB

    cudaFuncSetAttribute(fps_kernel, cudaFuncAttributeMaxDynamicSharedMemorySize, FPS_SMEM);
    cudaFuncSetAttribute(mlp_kernel, cudaFuncAttributeMaxDynamicSharedMemorySize, MLP_SMEM);

    fps_kernel<<<BATCH, 1024, FPS_SMEM>>>(xyz, new_xyz);
    query_kernel<<<(BATCH * NSAMP) / 8, 256>>>(xyz, new_xyz);
    mlp_kernel<<<(BATCH * NSAMP) / 8, 256, MLP_SMEM>>>(
        xyz, pts, w0, b0, w1, b1, w2, b2, new_xyz, new_pts);
}

// round 3
// speedup vs baseline: 1.4304x; 1.4304x over previous
#include <cuda_runtime.h>

#define BATCH 16
#define NPTS  4096
#define CIN   64
#define NSAMP 1024
#define KNBR  32
#define FULLM 0xffffffffu

// packed f32x2 helpers (per-lane IEEE rn -> bit-identical to scalar ops)
#define PACKF2(d, lo, hi)  asm("mov.b64 %0, {%1, %2};" : "=l"(d) : "f"(lo), "f"(hi))
#define UNPACKF2(lo, hi, s) asm("mov.b64 {%0, %1}, %2;" : "=f"(lo), "=f"(hi) : "l"(s))
#define ADD2(d, a, b) asm("add.rn.f32x2 %0, %1, %2;" : "=l"(d) : "l"(a), "l"(b))
#define MUL2(d, a, b) asm("mul.rn.f32x2 %0, %1, %2;" : "=l"(d) : "l"(a), "l"(b))
#define FMA2(d, a, b, c) asm("fma.rn.f32x2 %0, %1, %2, %3;" : "=l"(d) : "l"(a), "l"(b), "l"(c))

// scratch: ball-query neighbor indices
__device__ int d_ball[BATCH * NSAMP * KNBR];

// argmax combine: A side has the smaller index; strict > keeps min index on ties
#define AMAX(vA, jA, vB, jB, vO, jO) { bool g_ = ((vB) > (vA)); (vO) = g_ ? (vB) : (vA); (jO) = g_ ? (jB) : (jA); }

// ---------------------------------------------------------------------------
// Kernel 1: FPS. One block/batch, 256 threads x 16 pts. Packed-f32x2 distance,
// REDUX argmax (exact max-value/min-index), single barrier via double buffer.
// ---------------------------------------------------------------------------
__global__ __launch_bounds__(256) void fps_kernel(const float* __restrict__ xyz,
                                                  float* __restrict__ new_xyz)
{
    extern __shared__ float sm[];
    float* sxyz = sm;                              // 4096*3
    unsigned* redv = (unsigned*)(sm + NPTS * 3);   // [2][8]
    unsigned* redi = redv + 16;                    // [2][8]

    const int b = blockIdx.x, tid = threadIdx.x;
    const int lane = tid & 31;
    const float* gx = xyz + (size_t)b * NPTS * 3;

    for (int i = tid; i < NPTS * 3; i += 256) sxyz[i] = gx[i];
    __syncthreads();

    // register-resident points: slot j -> global index tid + j*256 (increasing)
    unsigned long long px[8], py[8], pz[8];
    float dist[16];
#pragma unroll
    for (int q = 0; q < 8; q++) {
        int p0 = tid + (2 * q) * 256, p1 = tid + (2 * q + 1) * 256;
        PACKF2(px[q], sxyz[3 * p0],     sxyz[3 * p1]);
        PACKF2(py[q], sxyz[3 * p0 + 1], sxyz[3 * p1 + 1]);
        PACKF2(pz[q], sxyz[3 * p0 + 2], sxyz[3 * p1 + 2]);
        dist[2 * q] = 1e10f; dist[2 * q + 1] = 1e10f;
    }

    int far = 0;
    for (int t = 0; t < NSAMP; t++) {
        float cx = sxyz[3 * far], cy = sxyz[3 * far + 1], cz = sxyz[3 * far + 2];
        if (tid == 0) {
            float* o = new_xyz + ((size_t)b * NSAMP + t) * 3;
            o[0] = cx; o[1] = cy; o[2] = cz;
        }
        unsigned long long ncx, ncy, ncz;
        float mx = -cx, my = -cy, mz = -cz;
        PACKF2(ncx, mx, mx); PACKF2(ncy, my, my); PACKF2(ncz, mz, mz);

        float v[16];
#pragma unroll
        for (int q = 0; q < 8; q++) {
            unsigned long long dx, dy, dz, xx, yy, zz, s, d2;
            ADD2(dx, px[q], ncx);          // p + (-c) == p - c exactly
            ADD2(dy, py[q], ncy);
            ADD2(dz, pz[q], ncz);
            MUL2(xx, dx, dx); MUL2(yy, dy, dy); MUL2(zz, dz, dz);
            ADD2(s, xx, yy); ADD2(d2, s, zz);     // (x²+y²)+z² order
            float d0, d1;
            UNPACKF2(d0, d1, d2);
            float n0 = fminf(dist[2 * q], d0);     dist[2 * q] = n0;     v[2 * q] = n0;
            float n1 = fminf(dist[2 * q + 1], d1); dist[2 * q + 1] = n1; v[2 * q + 1] = n1;
        }
        // tree argmax over 16 slots (min slot on ties -> min index)
        float va[8]; int ja[8];
#pragma unroll
        for (int q = 0; q < 8; q++) AMAX(v[2 * q], 2 * q, v[2 * q + 1], 2 * q + 1, va[q], ja[q]);
        float vb[4]; int jb[4];
#pragma unroll
        for (int q = 0; q < 4; q++) AMAX(va[2 * q], ja[2 * q], va[2 * q + 1], ja[2 * q + 1], vb[q], jb[q]);
        float vc0, vc1; int jc0, jc1;
        AMAX(vb[0], jb[0], vb[1], jb[1], vc0, jc0);
        AMAX(vb[2], jb[2], vb[3], jb[3], vc1, jc1);
        float mv; int mj;
        AMAX(vc0, jc0, vc1, jc1, mv, mj);
        int bi = tid + mj * 256;

        // warp argmax via REDUX (exact: max bits, then min index among equals)
        unsigned bits = __float_as_uint(mv);
        unsigned wmax = __reduce_max_sync(FULLM, bits);
        unsigned cand = (bits == wmax) ? (unsigned)bi : 0xffffffffu;
        unsigned wmin = __reduce_min_sync(FULLM, cand);

        const int pt = t & 1;
        if (lane == 0) {
            int w = tid >> 5;
            redv[pt * 8 + w] = wmax;
            redi[pt * 8 + w] = wmin;
        }
        __syncthreads();
        // every warp redundantly reduces the 8 candidates (no 2nd bar/broadcast)
        unsigned u  = (lane < 8) ? redv[pt * 8 + lane] : 0u;
        unsigned ui = (lane < 8) ? redi[pt * 8 + lane] : 0xffffffffu;
        unsigned gm = __reduce_max_sync(FULLM, u);
        unsigned ci = (u == gm) ? ui : 0xffffffffu;
        far = (int)__reduce_min_sync(FULLM, ci);
    }
}

// ---------------------------------------------------------------------------
// Kernel 2: ball query (unchanged).
// ---------------------------------------------------------------------------
__global__ __launch_bounds__(256) void query_kernel(const float* __restrict__ xyz,
                                                    const float* __restrict__ new_xyz)
{
    const int warp = threadIdx.x >> 5, lane = threadIdx.x & 31;
    const int gs = blockIdx.x * 8 + warp;
    const int b  = gs >> 10;
    const float* nc = new_xyz + (size_t)gs * 3;
    const float cx = nc[0], cy = nc[1], cz = nc[2];
    const float* gx = xyz + (size_t)b * NPTS * 3;
    int* out = d_ball + (size_t)gs * KNBR;
    const float R2 = 0.04f;

    int cnt = 0, first = -1;
    for (int base = 0; base < NPTS && cnt < KNBR; base += 32) {
        int j = base + lane;
        float dx = __fsub_rn(cx, gx[3 * j]);
        float dy = __fsub_rn(cy, gx[3 * j + 1]);
        float dz = __fsub_rn(cz, gx[3 * j + 2]);
        float d2 = __fadd_rn(__fadd_rn(__fmul_rn(dx, dx), __fmul_rn(dy, dy)),
                             __fmul_rn(dz, dz));
        bool in = (d2 <= R2);
        unsigned m = __ballot_sync(FULLM, in);
        int pos = cnt + __popc(m & ((1u << lane) - 1u));
        if (in && pos < KNBR) {
            out[pos] = j;
            if (pos == 0) first = j;
        }
        cnt += __popc(m);
    }
    unsigned hf = __ballot_sync(FULLM, first >= 0);
    int src = __ffs(hf) - 1;
    first = __shfl_sync(FULLM, first, src);
    int filled = cnt < KNBR ? cnt : KNBR;
    if (lane >= filled) out[lane] = first;
}

// ---------------------------------------------------------------------------
// Kernel 3: fused gather + MLP + max pool with fma.rn.f32x2 accumulators.
// Fixed layer-3 output scatter: lane j owns feature pair (2j, 2j+1);
// one float2 store per half covers all 64 features.
// ---------------------------------------------------------------------------
__global__ __launch_bounds__(256) void mlp_kernel(
    const float* __restrict__ xyz, const float* __restrict__ pts,
    const float* __restrict__ w0, const float* __restrict__ b0,
    const float* __restrict__ w1, const float* __restrict__ b1,
    const float* __restrict__ w2, const float* __restrict__ b2,
    const float* __restrict__ new_xyz, float* __restrict__ new_points)
{
    extern __shared__ float sm[];
    float* w0s = sm;                 // 67*64
    float* b0s = w0s + 4288;         // 64
    float* w1s = b0s + 64;           // 64*64
    float* b1s = w1s + 4096;         // 64
    float* w2s = b1s + 64;           // 64*128
    float* b2s = w2s + 8192;         // 128
    float* buf = b2s + 128;          // 67 * 256

    const int tid = threadIdx.x;
    for (int i = tid; i < 4288; i += 256) w0s[i] = w0[i];
    for (int i = tid; i < 64;   i += 256) b0s[i] = b0[i];
    for (int i = tid; i < 4096; i += 256) w1s[i] = w1[i];
    for (int i = tid; i < 64;   i += 256) b1s[i] = b1[i];
    for (int i = tid; i < 8192; i += 256) w2s[i] = w2[i];
    for (int i = tid; i < 128;  i += 256) b2s[i] = b2[i];

    const int warp = tid >> 5, lane = tid & 31;
    const int gs = blockIdx.x * 8 + warp;
    const int b  = gs >> 10;
    const int nid = d_ball[(size_t)gs * KNBR + lane];

    const float4* pr = (const float4*)(pts + ((size_t)b * NPTS + nid) * CIN);
#pragma unroll
    for (int q = 0; q < 16; q++) {
        float4 vv = pr[q];
        buf[(4 * q + 0) * 256 + tid] = vv.x;
        buf[(4 * q + 1) * 256 + tid] = vv.y;
        buf[(4 * q + 2) * 256 + tid] = vv.z;
        buf[(4 * q + 3) * 256 + tid] = vv.w;
    }
    {
        const float* xr = xyz + ((size_t)b * NPTS + nid) * 3;
        const float* nc = new_xyz + (size_t)gs * 3;
        buf[64 * 256 + tid] = __fsub_rn(xr[0], nc[0]);
        buf[65 * 256 + tid] = __fsub_rn(xr[1], nc[1]);
        buf[66 * 256 + tid] = __fsub_rn(xr[2], nc[2]);
    }
    __syncthreads();

    unsigned long long acc[32], xx;

    // ---- layer 1: 67 -> 64 ----
    {
        const unsigned long long* bb = (const unsigned long long*)b0s;
#pragma unroll
        for (int j = 0; j < 32; j++) acc[j] = bb[j];
        for (int c = 0; c < 67; c++) {
            float x = buf[c * 256 + tid];
            PACKF2(xx, x, x);
            const ulonglong2* wr = (const ulonglong2*)(w0s + c * 64);
#pragma unroll
            for (int j = 0; j < 16; j++) {
                ulonglong2 wv = wr[j];
                FMA2(acc[2 * j],     xx, wv.x, acc[2 * j]);
                FMA2(acc[2 * j + 1], xx, wv.y, acc[2 * j + 1]);
            }
        }
#pragma unroll
        for (int j = 0; j < 32; j++) {
            float lo, hi; UNPACKF2(lo, hi, acc[j]);
            buf[(2 * j) * 256 + tid]     = fmaxf(lo, 0.f);
            buf[(2 * j + 1) * 256 + tid] = fmaxf(hi, 0.f);
        }
    }

    // ---- layer 2: 64 -> 64 ----
    {
        const unsigned long long* bb = (const unsigned long long*)b1s;
#pragma unroll
        for (int j = 0; j < 32; j++) acc[j] = bb[j];
        for (int c = 0; c < 64; c++) {
            float x = buf[c * 256 + tid];
            PACKF2(xx, x, x);
            const ulonglong2* wr = (const ulonglong2*)(w1s + c * 64);
#pragma unroll
            for (int j = 0; j < 16; j++) {
                ulonglong2 wv = wr[j];
                FMA2(acc[2 * j],     xx, wv.x, acc[2 * j]);
                FMA2(acc[2 * j + 1], xx, wv.y, acc[2 * j + 1]);
            }
        }
#pragma unroll
        for (int j = 0; j < 32; j++) {
            float lo, hi; UNPACKF2(lo, hi, acc[j]);
            buf[(2 * j) * 256 + tid]     = fmaxf(lo, 0.f);
            buf[(2 * j + 1) * 256 + tid] = fmaxf(hi, 0.f);
        }
    }

    // ---- layer 3: 64 -> 128 (two halves of 64 features), relu + REDUX max
    // pool over k. Lane j collects feature pair (2j, 2j+1) -> float2 store. ----
    float* outp = new_points + (size_t)gs * 128;
#pragma unroll 1
    for (int h = 0; h < 2; h++) {
        const unsigned long long* bb = (const unsigned long long*)(b2s + h * 64);
#pragma unroll
        for (int j = 0; j < 32; j++) acc[j] = bb[j];
        for (int c = 0; c < 64; c++) {
            float x = buf[c * 256 + tid];
            PACKF2(xx, x, x);
            const ulonglong2* wr = (const ulonglong2*)(w2s + c * 128 + h * 64);
#pragma unroll
            for (int j = 0; j < 16; j++) {
                ulonglong2 wv = wr[j];
                FMA2(acc[2 * j],     xx, wv.x, acc[2 * j]);
                FMA2(acc[2 * j + 1], xx, wv.y, acc[2 * j + 1]);
            }
        }
        float r0 = 0.f, r1 = 0.f;
#pragma unroll
        for (int j = 0; j < 32; j++) {
            float lo, hi; UNPACKF2(lo, hi, acc[j]);
            unsigned m0 = __reduce_max_sync(FULLM, __float_as_uint(fmaxf(lo, 0.f)));
            unsigned m1 = __reduce_max_sync(FULLM, __float_as_uint(fmaxf(hi, 0.f)));
            if (lane == j) { r0 = __uint_as_float(m0); r1 = __uint_as_float(m1); }
        }
        float2 st; st.x = r0; st.y = r1;
        ((float2*)(outp + h * 64))[lane] = st;
    }
}

// ---------------------------------------------------------------------------
extern "C" void kernel_launch(void* const* d_in, const int* in_sizes, int n_in,
                              void* d_out, int out_size)
{
    (void)in_sizes; (void)n_in; (void)out_size;
    const float* xyz = (const float*)d_in[0];
    const float* pts = (const float*)d_in[1];
    const float* w0  = (const float*)d_in[2];
    const float* b0  = (const float*)d_in[3];
    const float* w1  = (const float*)d_in[4];
    const float* b1  = (const float*)d_in[5];
    const float* w2  = (const float*)d_in[6];
    const float* b2  = (const float*)d_in[7];

    float* out      = (float*)d_out;
    float* new_xyz  = out;
    float* new_pts  = out + (size_t)BATCH * NSAMP * 3;

    const int FPS_SMEM = (NPTS * 3) * 4 + 32 * 4;                                  // ~49.3 KB
    const int MLP_SMEM = (4288 + 64 + 4096 + 64 + 8192 + 128 + 67 * 256) * 4;      // ~136 KB

    cudaFuncSetAttribute(fps_kernel, cudaFuncAttributeMaxDynamicSharedMemorySize, FPS_SMEM);
    cudaFuncSetAttribute(mlp_kernel, cudaFuncAttributeMaxDynamicSharedMemorySize, MLP_SMEM);

    fps_kernel<<<BATCH, 256, FPS_SMEM>>>(xyz, new_xyz);
    query_kernel<<<(BATCH * NSAMP) / 8, 256>>>(xyz, new_xyz);
    mlp_kernel<<<(BATCH * NSAMP) / 8, 256, MLP_SMEM>>>(
        xyz, pts, w0, b0, w1, b1, w2, b2, new_xyz, new_pts);
}

// round 5
// speedup vs baseline: 2.4307x; 1.6993x over previous
#include <cuda_runtime.h>
#include <cuda_bf16.h>
#include <cstdint>

#define BATCH 16
#define NPTS  4096
#define CIN   64
#define NSAMP 1024
#define KNBR  32
#define FULLM 0xffffffffu

// ---------------- f32x2 helpers (FPS only) ----------------
#define PACKF2(d, lo, hi)  asm("mov.b64 %0, {%1, %2};" : "=l"(d) : "f"(lo), "f"(hi))
#define UNPACKF2(lo, hi, s) asm("mov.b64 {%0, %1}, %2;" : "=f"(lo), "=f"(hi) : "l"(s))
#define ADD2(d, a, b) asm("add.rn.f32x2 %0, %1, %2;" : "=l"(d) : "l"(a), "l"(b))
#define MUL2(d, a, b) asm("mul.rn.f32x2 %0, %1, %2;" : "=l"(d) : "l"(a), "l"(b))

__device__ int d_ball[BATCH * NSAMP * KNBR];

#define AMAX(vA, jA, vB, jB, vO, jO) { bool g_ = ((vB) > (vA)); (vO) = g_ ? (vB) : (vA); (jO) = g_ ? (jB) : (jA); }

// ---------------------------------------------------------------------------
// Kernel 1: FPS (unchanged — bit-exact, 377us)
// ---------------------------------------------------------------------------
__global__ __launch_bounds__(256) void fps_kernel(const float* __restrict__ xyz,
                                                  float* __restrict__ new_xyz)
{
    extern __shared__ float sm[];
    float* sxyz = sm;
    unsigned* redv = (unsigned*)(sm + NPTS * 3);
    unsigned* redi = redv + 16;

    const int b = blockIdx.x, tid = threadIdx.x;
    const int lane = tid & 31;
    const float* gx = xyz + (size_t)b * NPTS * 3;

    for (int i = tid; i < NPTS * 3; i += 256) sxyz[i] = gx[i];
    __syncthreads();

    unsigned long long px[8], py[8], pz[8];
    float dist[16];
#pragma unroll
    for (int q = 0; q < 8; q++) {
        int p0 = tid + (2 * q) * 256, p1 = tid + (2 * q + 1) * 256;
        PACKF2(px[q], sxyz[3 * p0],     sxyz[3 * p1]);
        PACKF2(py[q], sxyz[3 * p0 + 1], sxyz[3 * p1 + 1]);
        PACKF2(pz[q], sxyz[3 * p0 + 2], sxyz[3 * p1 + 2]);
        dist[2 * q] = 1e10f; dist[2 * q + 1] = 1e10f;
    }

    int far = 0;
    for (int t = 0; t < NSAMP; t++) {
        float cx = sxyz[3 * far], cy = sxyz[3 * far + 1], cz = sxyz[3 * far + 2];
        if (tid == 0) {
            float* o = new_xyz + ((size_t)b * NSAMP + t) * 3;
            o[0] = cx; o[1] = cy; o[2] = cz;
        }
        unsigned long long ncx, ncy, ncz;
        float mx = -cx, my = -cy, mz = -cz;
        PACKF2(ncx, mx, mx); PACKF2(ncy, my, my); PACKF2(ncz, mz, mz);

        float v[16];
#pragma unroll
        for (int q = 0; q < 8; q++) {
            unsigned long long dx, dy, dz, xx, yy, zz, s, d2;
            ADD2(dx, px[q], ncx);
            ADD2(dy, py[q], ncy);
            ADD2(dz, pz[q], ncz);
            MUL2(xx, dx, dx); MUL2(yy, dy, dy); MUL2(zz, dz, dz);
            ADD2(s, xx, yy); ADD2(d2, s, zz);
            float d0, d1;
            UNPACKF2(d0, d1, d2);
            float n0 = fminf(dist[2 * q], d0);     dist[2 * q] = n0;     v[2 * q] = n0;
            float n1 = fminf(dist[2 * q + 1], d1); dist[2 * q + 1] = n1; v[2 * q + 1] = n1;
        }
        float va[8]; int ja[8];
#pragma unroll
        for (int q = 0; q < 8; q++) AMAX(v[2 * q], 2 * q, v[2 * q + 1], 2 * q + 1, va[q], ja[q]);
        float vb[4]; int jb[4];
#pragma unroll
        for (int q = 0; q < 4; q++) AMAX(va[2 * q], ja[2 * q], va[2 * q + 1], ja[2 * q + 1], vb[q], jb[q]);
        float vc0, vc1; int jc0, jc1;
        AMAX(vb[0], jb[0], vb[1], jb[1], vc0, jc0);
        AMAX(vb[2], jb[2], vb[3], jb[3], vc1, jc1);
        float mv; int mj;
        AMAX(vc0, jc0, vc1, jc1, mv, mj);
        int bi = tid + mj * 256;

        unsigned bits = __float_as_uint(mv);
        unsigned wmax = __reduce_max_sync(FULLM, bits);
        unsigned cand = (bits == wmax) ? (unsigned)bi : 0xffffffffu;
        unsigned wmin = __reduce_min_sync(FULLM, cand);

        const int pt = t & 1;
        if (lane == 0) {
            int w = tid >> 5;
            redv[pt * 8 + w] = wmax;
            redi[pt * 8 + w] = wmin;
        }
        __syncthreads();
        unsigned u  = (lane < 8) ? redv[pt * 8 + lane] : 0u;
        unsigned ui = (lane < 8) ? redi[pt * 8 + lane] : 0xffffffffu;
        unsigned gm = __reduce_max_sync(FULLM, u);
        unsigned ci = (u == gm) ? ui : 0xffffffffu;
        far = (int)__reduce_min_sync(FULLM, ci);
    }
}

// ---------------------------------------------------------------------------
// Kernel 2: ball query (unchanged)
// ---------------------------------------------------------------------------
__global__ __launch_bounds__(256) void query_kernel(const float* __restrict__ xyz,
                                                    const float* __restrict__ new_xyz)
{
    const int warp = threadIdx.x >> 5, lane = threadIdx.x & 31;
    const int gs = blockIdx.x * 8 + warp;
    const int b  = gs >> 10;
    const float* nc = new_xyz + (size_t)gs * 3;
    const float cx = nc[0], cy = nc[1], cz = nc[2];
    const float* gx = xyz + (size_t)b * NPTS * 3;
    int* out = d_ball + (size_t)gs * KNBR;
    const float R2 = 0.04f;

    int cnt = 0, first = -1;
    for (int base = 0; base < NPTS && cnt < KNBR; base += 32) {
        int j = base + lane;
        float dx = __fsub_rn(cx, gx[3 * j]);
        float dy = __fsub_rn(cy, gx[3 * j + 1]);
        float dz = __fsub_rn(cz, gx[3 * j + 2]);
        float d2 = __fadd_rn(__fadd_rn(__fmul_rn(dx, dx), __fmul_rn(dy, dy)),
                             __fmul_rn(dz, dz));
        bool in = (d2 <= R2);
        unsigned m = __ballot_sync(FULLM, in);
        int pos = cnt + __popc(m & ((1u << lane) - 1u));
        if (in && pos < KNBR) {
            out[pos] = j;
            if (pos == 0) first = j;
        }
        cnt += __popc(m);
    }
    unsigned hf = __ballot_sync(FULLM, first >= 0);
    int src = __ffs(hf) - 1;
    first = __shfl_sync(FULLM, first, src);
    int filled = cnt < KNBR ? cnt : KNBR;
    if (lane >= filled) out[lane] = first;
}

// ---------------------------------------------------------------------------
// Kernel 3: MLP via mma.sync (m16n8k16 bf16, 3-term hi/mid split).
// warp = centroid (M=32 neighbors), weights transposed [n][k] in SMEM,
// activations per-warp staged hi/mid, maxpool via fragment + butterfly.
// ---------------------------------------------------------------------------
#define ASTRIDE  176          // 80 bf16 cols padded; conflict-free ldmatrix
#define WSTR1    176
#define WSTR23   144
#define SM_BIAS  0            // 256 floats = 1024B
#define SM_W1H   1024
#define SM_W1M   12288
#define SM_W2H   23552
#define SM_W2M   32768
#define SM_W3H   41984
#define SM_W3M   60416
#define SM_ACT   78848
#define ACTW     11264        // per warp: 32*176 hi + 32*176 mid
#define SM_MLP_END (78848 + 8 * ACTW)   // 168960

__device__ __forceinline__ unsigned pk_hi(float a, float b) {
    __nv_bfloat16 ha = __float2bfloat16_rn(a), hb = __float2bfloat16_rn(b);
    return ((unsigned)__bfloat16_as_ushort(hb) << 16) | __bfloat16_as_ushort(ha);
}
__device__ __forceinline__ unsigned pk_mid(float a, float b) {
    __nv_bfloat16 ha = __float2bfloat16_rn(a), hb = __float2bfloat16_rn(b);
    __nv_bfloat16 ma = __float2bfloat16_rn(a - __bfloat162float(ha));
    __nv_bfloat16 mb = __float2bfloat16_rn(b - __bfloat162float(hb));
    return ((unsigned)__bfloat16_as_ushort(mb) << 16) | __bfloat16_as_ushort(ma);
}
__device__ __forceinline__ uint32_t smem_u32(const void* p) {
    uint32_t a;
    asm("{ .reg .u64 t; cvta.to.shared.u64 t, %1; cvt.u32.u64 %0, t; }" : "=r"(a) : "l"(p));
    return a;
}
__device__ __forceinline__ void ldsm4(uint32_t* r, uint32_t addr) {
    asm volatile("ldmatrix.sync.aligned.m8n8.x4.shared.b16 {%0,%1,%2,%3}, [%4];"
        : "=r"(r[0]), "=r"(r[1]), "=r"(r[2]), "=r"(r[3]) : "r"(addr));
}
__device__ __forceinline__ void ldsm2(uint32_t* r, uint32_t addr) {
    asm volatile("ldmatrix.sync.aligned.m8n8.x2.shared.b16 {%0,%1}, [%2];"
        : "=r"(r[0]), "=r"(r[1]) : "r"(addr));
}
__device__ __forceinline__ void mma_bf16(float* d, const uint32_t* a, const uint32_t* b) {
    asm volatile("mma.sync.aligned.m16n8k16.row.col.f32.bf16.bf16.f32 "
        "{%0,%1,%2,%3}, {%4,%5,%6,%7}, {%8,%9}, {%0,%1,%2,%3};"
        : "+f"(d[0]), "+f"(d[1]), "+f"(d[2]), "+f"(d[3])
        : "r"(a[0]), "r"(a[1]), "r"(a[2]), "r"(a[3]), "r"(b[0]), "r"(b[1]));
}

template<int KT, int WSTR>
__device__ __forceinline__ void run_layer(uint32_t aH, uint32_t aM,
                                          uint32_t wHb, uint32_t wMb,
                                          float acc[2][8][4])
{
#pragma unroll
    for (int m = 0; m < 2; m++)
#pragma unroll
        for (int n = 0; n < 8; n++)
#pragma unroll
            for (int q = 0; q < 4; q++) acc[m][n][q] = 0.f;
#pragma unroll
    for (int k = 0; k < KT; k++) {
        uint32_t ah[2][4], am[2][4];
        ldsm4(ah[0], aH + k * 32);
        ldsm4(ah[1], aH + 16 * ASTRIDE + k * 32);
        ldsm4(am[0], aM + k * 32);
        ldsm4(am[1], aM + 16 * ASTRIDE + k * 32);
#pragma unroll
        for (int n = 0; n < 8; n++) {
            uint32_t bh[2], bm[2];
            ldsm2(bh, wHb + n * 8 * WSTR + k * 32);
            ldsm2(bm, wMb + n * 8 * WSTR + k * 32);
#pragma unroll
            for (int m = 0; m < 2; m++) {
                mma_bf16(acc[m][n], ah[m], bh);
                mma_bf16(acc[m][n], am[m], bh);
                mma_bf16(acc[m][n], ah[m], bm);
            }
        }
    }
}

__device__ __forceinline__ void epi_store(float acc[2][8][4],
    char* actH, char* actM, const float* bias, int lane)
{
    const int cg = lane & 3, rg = lane >> 2;
#pragma unroll
    for (int m = 0; m < 2; m++) {
#pragma unroll
        for (int n = 0; n < 8; n++) {
            int n0 = n * 8 + 2 * cg;
            float b0v = bias[n0], b1v = bias[n0 + 1];
            float x0 = fmaxf(acc[m][n][0] + b0v, 0.f);
            float x1 = fmaxf(acc[m][n][1] + b1v, 0.f);
            float x2 = fmaxf(acc[m][n][2] + b0v, 0.f);
            float x3 = fmaxf(acc[m][n][3] + b1v, 0.f);
            int r0 = m * 16 + rg, r1 = r0 + 8;
            *(uint32_t*)(actH + r0 * ASTRIDE + n0 * 2) = pk_hi(x0, x1);
            *(uint32_t*)(actH + r1 * ASTRIDE + n0 * 2) = pk_hi(x2, x3);
            *(uint32_t*)(actM + r0 * ASTRIDE + n0 * 2) = pk_mid(x0, x1);
            *(uint32_t*)(actM + r1 * ASTRIDE + n0 * 2) = pk_mid(x2, x3);
        }
    }
}

__device__ __forceinline__ void epi_max(float acc[2][8][4], const float* bias,
                                        float* outp, int nbase, int lane)
{
    const int cg = lane & 3;
#pragma unroll
    for (int n = 0; n < 8; n++) {
        int n0 = nbase + n * 8 + 2 * cg;
        float b0v = bias[n0], b1v = bias[n0 + 1];
        float v0 = fmaxf(fmaxf(acc[0][n][0] + b0v, 0.f), fmaxf(acc[0][n][2] + b0v, 0.f));
        v0 = fmaxf(v0, fmaxf(fmaxf(acc[1][n][0] + b0v, 0.f), fmaxf(acc[1][n][2] + b0v, 0.f)));
        float v1 = fmaxf(fmaxf(acc[0][n][1] + b1v, 0.f), fmaxf(acc[0][n][3] + b1v, 0.f));
        v1 = fmaxf(v1, fmaxf(fmaxf(acc[1][n][1] + b1v, 0.f), fmaxf(acc[1][n][3] + b1v, 0.f)));
#pragma unroll
        for (int o = 4; o <= 16; o <<= 1) {
            v0 = fmaxf(v0, __shfl_xor_sync(FULLM, v0, o));
            v1 = fmaxf(v1, __shfl_xor_sync(FULLM, v1, o));
        }
        if (lane < 4) { outp[n0] = v0; outp[n0 + 1] = v1; }
    }
}

__global__ __launch_bounds__(256) void mlp_kernel(
    const float* __restrict__ xyz, const float* __restrict__ pts,
    const float* __restrict__ w0, const float* __restrict__ b0,
    const float* __restrict__ w1, const float* __restrict__ b1,
    const float* __restrict__ w2, const float* __restrict__ b2,
    const float* __restrict__ new_xyz, float* __restrict__ new_points)
{
    extern __shared__ char smem[];
    const uint32_t sb = smem_u32(smem);
    const int tid = threadIdx.x, wid = tid >> 5, lane = tid & 31;

    // ---- stage biases ----
    float* b0s = (float*)(smem + SM_BIAS);
    float* b1s = b0s + 64;
    float* b2s = b1s + 64;
    if (tid < 64) { b0s[tid] = b0[tid]; b1s[tid] = b1[tid]; }
    if (tid < 128) b2s[tid] = b2[tid];

    // ---- stage transposed weights, hi/mid bf16 ----
    for (int idx = tid; idx < 64 * 80; idx += 256) {
        int n = idx / 80, k = idx - n * 80;
        float w = (k < 67) ? w0[k * 64 + n] : 0.f;
        __nv_bfloat16 h = __float2bfloat16_rn(w);
        __nv_bfloat16 m = __float2bfloat16_rn(w - __bfloat162float(h));
        *(unsigned short*)(smem + SM_W1H + n * WSTR1 + k * 2) = __bfloat16_as_ushort(h);
        *(unsigned short*)(smem + SM_W1M + n * WSTR1 + k * 2) = __bfloat16_as_ushort(m);
    }
    for (int idx = tid; idx < 64 * 64; idx += 256) {
        int n = idx >> 6, k = idx & 63;
        float w = w1[k * 64 + n];
        __nv_bfloat16 h = __float2bfloat16_rn(w);
        __nv_bfloat16 m = __float2bfloat16_rn(w - __bfloat162float(h));
        *(unsigned short*)(smem + SM_W2H + n * WSTR23 + k * 2) = __bfloat16_as_ushort(h);
        *(unsigned short*)(smem + SM_W2M + n * WSTR23 + k * 2) = __bfloat16_as_ushort(m);
    }
    for (int idx = tid; idx < 128 * 64; idx += 256) {
        int n = idx >> 6, k = idx & 63;
        float w = w2[k * 128 + n];
        __nv_bfloat16 h = __float2bfloat16_rn(w);
        __nv_bfloat16 m = __float2bfloat16_rn(w - __bfloat162float(h));
        *(unsigned short*)(smem + SM_W3H + n * WSTR23 + k * 2) = __bfloat16_as_ushort(h);
        *(unsigned short*)(smem + SM_W3M + n * WSTR23 + k * 2) = __bfloat16_as_ushort(m);
    }
    __syncthreads();

    // ---- per-lane ldmatrix base addresses ----
    char* actHp = smem + SM_ACT + wid * ACTW;
    char* actMp = actHp + 5632;
    const uint32_t actH_u = sb + SM_ACT + wid * ACTW;
    const uint32_t actM_u = actH_u + 5632;
    const uint32_t aH = actH_u + (lane & 15) * ASTRIDE + (lane >> 4) * 16;
    const uint32_t aM = actM_u + (lane & 15) * ASTRIDE + (lane >> 4) * 16;
    const int bl = lane & 15;
    const uint32_t wl1 = (bl & 7) * WSTR1  + ((bl >> 3) & 1) * 16;
    const uint32_t wl2 = (bl & 7) * WSTR23 + ((bl >> 3) & 1) * 16;
    const uint32_t w1H = sb + SM_W1H + wl1, w1M = sb + SM_W1M + wl1;
    const uint32_t w2H = sb + SM_W2H + wl2, w2M = sb + SM_W2M + wl2;
    const uint32_t w3H = sb + SM_W3H + wl2, w3M = sb + SM_W3M + wl2;

#pragma unroll 1
    for (int cc = 0; cc < 4; cc++) {
        const int centroid = blockIdx.x * 32 + wid * 4 + cc;
        const int b = centroid >> 10;
        const int nid = d_ball[(size_t)centroid * KNBR + lane];

        __syncwarp();
        // ---- gather: 64 features + 3 rel coords, pad to 80; hi/mid split ----
        {
            float arr[80];
            const float4* pr = (const float4*)(pts + ((size_t)b * NPTS + nid) * CIN);
#pragma unroll
            for (int q = 0; q < 16; q++) {
                float4 v = pr[q];
                arr[4 * q] = v.x; arr[4 * q + 1] = v.y; arr[4 * q + 2] = v.z; arr[4 * q + 3] = v.w;
            }
            const float* xr = xyz + ((size_t)b * NPTS + nid) * 3;
            const float* nc = new_xyz + (size_t)centroid * 3;
            arr[64] = __fsub_rn(xr[0], nc[0]);
            arr[65] = __fsub_rn(xr[1], nc[1]);
            arr[66] = __fsub_rn(xr[2], nc[2]);
#pragma unroll
            for (int i = 67; i < 80; i++) arr[i] = 0.f;

            uint32_t* rowH = (uint32_t*)(actHp + lane * ASTRIDE);
            uint32_t* rowM = (uint32_t*)(actMp + lane * ASTRIDE);
#pragma unroll
            for (int i = 0; i < 40; i++) {
                rowH[i] = pk_hi(arr[2 * i], arr[2 * i + 1]);
                rowM[i] = pk_mid(arr[2 * i], arr[2 * i + 1]);
            }
        }
        __syncwarp();

        float acc[2][8][4];
        // layer 1: K=80, N=64
        run_layer<5, WSTR1>(aH, aM, w1H, w1M, acc);
        __syncwarp();
        epi_store(acc, actHp, actMp, b0s, lane);
        __syncwarp();
        // layer 2: K=64, N=64
        run_layer<4, WSTR23>(aH, aM, w2H, w2M, acc);
        __syncwarp();
        epi_store(acc, actHp, actMp, b1s, lane);
        __syncwarp();
        // layer 3: K=64, N=128 (two N-halves) + maxpool
        float* outp = new_points + (size_t)centroid * 128;
        run_layer<4, WSTR23>(aH, aM, w3H, w3M, acc);
        epi_max(acc, b2s, outp, 0, lane);
        run_layer<4, WSTR23>(aH, aM, w3H + 64 * WSTR23, w3M + 64 * WSTR23, acc);
        epi_max(acc, b2s, outp, 64, lane);
    }
}

// ---------------------------------------------------------------------------
extern "C" void kernel_launch(void* const* d_in, const int* in_sizes, int n_in,
                              void* d_out, int out_size)
{
    (void)in_sizes; (void)n_in; (void)out_size;
    const float* xyz = (const float*)d_in[0];
    const float* pts = (const float*)d_in[1];
    const float* w0  = (const float*)d_in[2];
    const float* b0  = (const float*)d_in[3];
    const float* w1  = (const float*)d_in[4];
    const float* b1  = (const float*)d_in[5];
    const float* w2  = (const float*)d_in[6];
    const float* b2  = (const float*)d_in[7];

    float* out      = (float*)d_out;
    float* new_xyz  = out;
    float* new_pts  = out + (size_t)BATCH * NSAMP * 3;

    const int FPS_SMEM = (NPTS * 3) * 4 + 32 * 4;
    const int MLP_SMEM = SM_MLP_END;

    cudaFuncSetAttribute(fps_kernel, cudaFuncAttributeMaxDynamicSharedMemorySize, FPS_SMEM);
    cudaFuncSetAttribute(mlp_kernel, cudaFuncAttributeMaxDynamicSharedMemorySize, MLP_SMEM);

    fps_kernel<<<BATCH, 256, FPS_SMEM>>>(xyz, new_xyz);
    query_kernel<<<(BATCH * NSAMP) / 8, 256>>>(xyz, new_xyz);
    mlp_kernel<<<(BATCH * NSAMP) / 32, 256, MLP_SMEM>>>(
        xyz, pts, w0, b0, w1, b1, w2, b2, new_xyz, new_pts);
}